// round 13
// baseline (speedup 1.0000x reference)
#include <cuda_runtime.h>
#include <cuda_fp16.h>
#include <math.h>
#include <stdint.h>

// ---------------------------------------------------------------------------
// Gate_14293651161746 (round 13): 3-stage single-barrier pipeline.
//   W pre-split ONCE into two fp16 planes (64x main, 2048x residual scale).
//   GEMM streams B planes global->regs->SMEM raw; X split inline.
//     a = a0 + a1s/2048 ; 64*b = b0 + b1s/2048
//     accA = sum a0*b0 ; accB = sum (a0*b1s + a1s*b0)
//     logit = (accA + accB/2048)/64, drained to fp32 SMEM every k=256
// Output: [weights (T*8) fp32][indices (T*8) as fp32]
// ---------------------------------------------------------------------------

#define FULLMASK 0xFFFFFFFFu
#define RSCALE 2048.0f
#define RSCALE_INV (1.0f / 2048.0f)
#define BSCALE 64.0f
#define BSCALE_INV (1.0f / 64.0f)

#define DD 7168
#define EE 256

static __device__ __half g_B0[(size_t)EE * DD];   // RN16(64*w)
static __device__ __half g_B1[(size_t)EE * DD];   // RN16((64w - b0)*2048)

// ---- SMEM layout ----------------------------------------------------------
// Stage buffer (fp16 tiles, rows padded to 40 halves = 80 B):
//   A0: 64 x 40 = 5120 B (off 0) | A1s: 5120 B (off 5120)
//   B0: 256 x 40 = 20480 B (off 10240) | B1s: 20480 B (off 30720)
// THREE stages (single barrier per stage), then fp32 logits acc [64][264].
#define STAGE_BYTES 51200
#define LOGITS_OFF  (3 * STAGE_BYTES)              // 153600
#define SMEM_BYTES  (LOGITS_OFF + 64 * 264 * 4)    // 221184

__device__ __forceinline__ uint32_t smem_to_u32(const void* p) {
    uint32_t a;
    asm("{ .reg .u64 t; cvta.to.shared.u64 t, %1; cvt.u32.u64 %0, t; }" : "=r"(a) : "l"(p));
    return a;
}

#define LDM4(r, addr) \
    asm volatile("ldmatrix.sync.aligned.m8n8.x4.shared.b16 {%0,%1,%2,%3}, [%4];" \
                 : "=r"((r)[0]), "=r"((r)[1]), "=r"((r)[2]), "=r"((r)[3]) \
                 : "r"(addr))

#define MMA16816(c, a, b0, b1) \
    asm volatile("mma.sync.aligned.m16n8k16.row.col.f32.f16.f16.f32 " \
                 "{%0,%1,%2,%3}, {%4,%5,%6,%7}, {%8,%9}, {%0,%1,%2,%3};" \
                 : "+f"((c)[0]), "+f"((c)[1]), "+f"((c)[2]), "+f"((c)[3]) \
                 : "r"((a)[0]), "r"((a)[1]), "r"((a)[2]), "r"((a)[3]), \
                   "r"(b0), "r"(b1))

// split one float4 into main fp16 quad + scaled-residual fp16 quad
__device__ __forceinline__ void split4s(float4 v, uint2& lo, uint2& hi) {
    __half a0 = __float2half_rn(v.x), b0 = __float2half_rn(v.y);
    __half c0 = __float2half_rn(v.z), d0 = __float2half_rn(v.w);
    __half a1 = __float2half_rn((v.x - __half2float(a0)) * RSCALE);
    __half b1 = __float2half_rn((v.y - __half2float(b0)) * RSCALE);
    __half c1 = __float2half_rn((v.z - __half2float(c0)) * RSCALE);
    __half d1 = __float2half_rn((v.w - __half2float(d0)) * RSCALE);
    lo.x = (uint32_t)__half_as_ushort(a0) | ((uint32_t)__half_as_ushort(b0) << 16);
    lo.y = (uint32_t)__half_as_ushort(c0) | ((uint32_t)__half_as_ushort(d0) << 16);
    hi.x = (uint32_t)__half_as_ushort(a1) | ((uint32_t)__half_as_ushort(b1) << 16);
    hi.y = (uint32_t)__half_as_ushort(c1) | ((uint32_t)__half_as_ushort(d1) << 16);
}

// ---- presplit W -> two fp16 planes ----------------------------------------
__global__ void __launch_bounds__(256)
presplit_kernel(const float* __restrict__ W, __half* __restrict__ B0,
                __half* __restrict__ B1, int n4) {
    int i = blockIdx.x * blockDim.x + threadIdx.x;
    if (i >= n4) return;
    float4 v = ((const float4*)W)[i];
    v.x *= BSCALE; v.y *= BSCALE; v.z *= BSCALE; v.w *= BSCALE;
    uint2 lo, hi;
    split4s(v, lo, hi);
    ((uint2*)B0)[i] = lo;
    ((uint2*)B1)[i] = hi;
}

__global__ void __launch_bounds__(256, 1)
moe_gate_kernel(const float* __restrict__ X, const __half* __restrict__ B0g,
                const __half* __restrict__ B1g, const float* __restrict__ bias,
                float* __restrict__ outW, float* __restrict__ outI,
                int T, int E, int D) {
    extern __shared__ char smem[];
    const uint32_t sb = smem_to_u32(smem);
    const int tid = threadIdx.x;
    const int lane = tid & 31;
    const int wid = tid >> 5;
    const int wm = wid >> 2;   // 0..1  -> 32-row slice
    const int wn = wid & 3;    // 0..3  -> 64-col slice
    const int bm = blockIdx.x * 64;

    float* ls = (float*)(smem + LOGITS_OFF);   // [64][264] fp32 logits accumulator
#pragma unroll
    for (int i = 0; i < 66; i++) ls[tid + i * 256] = 0.0f;
    __syncthreads();   // ls zeroed before any drain (drains are barrier-free)

    float accA[2][8][4];
    float accB[2][8][4];
#pragma unroll
    for (int i = 0; i < 2; i++)
#pragma unroll
        for (int j = 0; j < 8; j++)
#pragma unroll
            for (int k = 0; k < 4; k++) { accA[i][j][k] = 0.0f; accB[i][j][k] = 0.0f; }

    // A staging: element i = tid + j*256; row = i>>3, chunk col = (i&7)*4
    const int grow = tid >> 3;
    const int gcol = (tid & 7) * 4;
    const float* Ag = X + (size_t)(bm + grow) * D + gcol;
    const size_t jstride = (size_t)32 * D;
    const uint32_t sts_off = (uint32_t)(grow * 80 + (tid & 7) * 8);

    // B staging: per plane 256 rows x 2x16B chunks; thread -> row tid>>2 (+64/j)
    const int brow = tid >> 2;
    const int bchunk = (tid & 3) * 8;
    const __half* B0p = B0g + (size_t)brow * D + bchunk;
    const __half* B1p = B1g + (size_t)brow * D + bchunk;
    const uint32_t bdst = (uint32_t)(brow * 80 + bchunk * 2);
    const size_t bjstride = (size_t)64 * D;

    const int NS = D / 32;
    float4 ra[2];
    uint4 rb0[4], rb1[4];

    // ldmatrix per-thread base offsets (bytes within a stage buffer)
    const int q = lane >> 3;
    const uint32_t pa = (uint32_t)((wm * 32 + (q & 1) * 8 + (lane & 7)) * 80 + (q >> 1) * 16);
    const uint32_t pb = (uint32_t)((wn * 64 + ((q >> 1) & 1) * 8 + (lane & 7)) * 80 + (q & 1) * 16);

    // fragment element -> logits row/col (for chunk drains)
    const int drow = wm * 32 + (lane >> 2);
    const int dcol = wn * 64 + (lane & 3) * 2;

    // prologue LDG (stage 0)
#pragma unroll
    for (int j = 0; j < 2; j++) ra[j] = *(const float4*)(Ag + j * jstride);
#pragma unroll
    for (int j = 0; j < 4; j++) {
        rb0[j] = *(const uint4*)(B0p + j * bjstride);
        rb1[j] = *(const uint4*)(B1p + j * bjstride);
    }

    uint32_t boff = 0;  // (s % 3) * STAGE_BYTES, tracked incrementally
    for (int s = 0; s < NS; s++) {
        // ---- STS stage s: A split fp32->fp16 pair; B raw 16B -------------
        {
            char* bufc = smem + boff;
#pragma unroll
            for (int j = 0; j < 2; j++) {
                uint2 lo, hi;
                split4s(ra[j], lo, hi);
                uint32_t o = sts_off + (uint32_t)j * (32 * 80);
                *(uint2*)(bufc + o) = lo;           // A0
                *(uint2*)(bufc + 5120 + o) = hi;    // A1s
            }
#pragma unroll
            for (int j = 0; j < 4; j++) {
                uint32_t o = bdst + (uint32_t)j * (64 * 80);
                *(uint4*)(bufc + 10240 + o) = rb0[j];   // B0
                *(uint4*)(bufc + 30720 + o) = rb1[j];   // B1s
            }
        }

        // ---- LDG stage s+1 (before barrier: hides latency under the wait)
        if (s + 1 < NS) {
            const int k0 = (s + 1) * 32;
#pragma unroll
            for (int j = 0; j < 2; j++) ra[j] = *(const float4*)(Ag + k0 + j * jstride);
#pragma unroll
            for (int j = 0; j < 4; j++) {
                rb0[j] = *(const uint4*)(B0p + k0 + j * bjstride);
                rb1[j] = *(const uint4*)(B1p + k0 + j * bjstride);
            }
        }

        __syncthreads();   // single barrier: stage s visible; 3 buffers make it safe

        // ---- MMA over stage s: 2 k16-steps (overlaps others' STS of s+1) --
        const uint32_t abase = sb + boff + pa;
        const uint32_t bbase = sb + boff + 10240 + pb;
#pragma unroll
        for (int ks = 0; ks < 2; ks++) {
            uint32_t a0f[2][4], a1f[2][4];
#pragma unroll
            for (int mt = 0; mt < 2; mt++) {
                uint32_t aaddr = abase + (uint32_t)(mt * 1280 + ks * 32);
                LDM4(a0f[mt], aaddr);
                LDM4(a1f[mt], aaddr + 5120);
            }
#pragma unroll
            for (int np = 0; np < 4; np++) {
                uint32_t b0f[4], b1f[4];
                uint32_t baddr = bbase + (uint32_t)(np * 1280 + ks * 32);
                LDM4(b0f, baddr);
                LDM4(b1f, baddr + 20480);
#pragma unroll
                for (int mt = 0; mt < 2; mt++) {
                    MMA16816(accA[mt][2 * np],     a0f[mt], b0f[0], b0f[1]);
                    MMA16816(accA[mt][2 * np + 1], a0f[mt], b0f[2], b0f[3]);
                    MMA16816(accB[mt][2 * np],     a1f[mt], b0f[0], b0f[1]);
                    MMA16816(accB[mt][2 * np + 1], a1f[mt], b0f[2], b0f[3]);
                    MMA16816(accB[mt][2 * np],     a0f[mt], b1f[0], b1f[1]);
                    MMA16816(accB[mt][2 * np + 1], a0f[mt], b1f[2], b1f[3]);
                }
            }
        }

        // ---- chunk drain every 8 stages (k=256): acc -> fp32 SMEM --------
        // (each warp owns its ls cells exclusively -> no barrier needed)
        if ((s & 7) == 7) {
#pragma unroll
            for (int mt = 0; mt < 2; mt++) {
#pragma unroll
                for (int np = 0; np < 4; np++) {
#pragma unroll
                    for (int nt = 0; nt < 2; nt++) {
                        float* cA = accA[mt][2 * np + nt];
                        float* cB = accB[mt][2 * np + nt];
                        int row = drow + mt * 16;
                        int col = dcol + np * 16 + nt * 8;
                        ls[row * 264 + col]           += cA[0] + cB[0] * RSCALE_INV;
                        ls[row * 264 + col + 1]       += cA[1] + cB[1] * RSCALE_INV;
                        ls[(row + 8) * 264 + col]     += cA[2] + cB[2] * RSCALE_INV;
                        ls[(row + 8) * 264 + col + 1] += cA[3] + cB[3] * RSCALE_INV;
                        cA[0] = cA[1] = cA[2] = cA[3] = 0.0f;
                        cB[0] = cB[1] = cB[2] = cB[3] = 0.0f;
                    }
                }
            }
        }

        boff += STAGE_BYTES;
        if (boff == 3 * STAGE_BYTES) boff = 0;
    }
    __syncthreads();

    // ---- gate: one warp per token, 8 tokens per warp ----------------------
    float4 c0 = *(const float4*)(bias + lane * 8);
    float4 c1 = *(const float4*)(bias + lane * 8 + 4);
    const float bs[8] = {c0.x, c0.y, c0.z, c0.w, c1.x, c1.y, c1.z, c1.w};

    for (int r = 0; r < 8; r++) {
        const int tl = r * 8 + wid;
        const float* Lp = ls + tl * 264 + lane * 8;
        float4 v0 = *(const float4*)Lp;
        float4 v1 = *(const float4*)(Lp + 4);
        float lg[8] = {v0.x, v0.y, v0.z, v0.w, v1.x, v1.y, v1.z, v1.w};

        float sig[8], s[8];
#pragma unroll
        for (int j = 0; j < 8; j++) {
            float logit = lg[j] * BSCALE_INV;      // undo exact B pre-scale
            sig[j] = 1.0f / (1.0f + expf(-logit));
            s[j] = sig[j] + bs[j];
        }

        float t1 = -INFINITY, t2 = -INFINITY;
#pragma unroll
        for (int j = 0; j < 8; j++) {
            float v = s[j];
            if (v > t1) { t2 = t1; t1 = v; }
            else if (v > t2) { t2 = v; }
        }
#pragma unroll
        for (int off = 1; off < 4; off <<= 1) {
            float o1 = __shfl_xor_sync(FULLMASK, t1, off);
            float o2 = __shfl_xor_sync(FULLMASK, t2, off);
            float m1 = fmaxf(t1, o1);
            float m2 = fmaxf(fminf(t1, o1), (t1 > o1) ? t2 : o2);
            t1 = m1; t2 = m2;
        }
        float gsc = t1 + t2;

        float gs[8];
#pragma unroll
        for (int g = 0; g < 8; g++) gs[g] = __shfl_sync(FULLMASK, gsc, g * 4);

        int keepmask = 0;
#pragma unroll
        for (int rr = 0; rr < 4; rr++) {
            float best = -INFINITY; int bg = 0;
#pragma unroll
            for (int g = 0; g < 8; g++)
                if (!((keepmask >> g) & 1) && gs[g] > best) { best = gs[g]; bg = g; }
            keepmask |= 1 << bg;
        }
        const bool mk = (keepmask >> (lane >> 2)) & 1;
        float sm[8];
#pragma unroll
        for (int j = 0; j < 8; j++) sm[j] = mk ? s[j] : 0.0f;

        int takenmask = 0;
        float wsel[8]; int isel[8]; float wsum = 0.0f;
#pragma unroll
        for (int rr = 0; rr < 8; rr++) {
            float bv = -INFINITY; int bi = 0x7FFFFFFF;
#pragma unroll
            for (int j = 0; j < 8; j++)
                if (!((takenmask >> j) & 1) && sm[j] > bv) { bv = sm[j]; bi = lane * 8 + j; }
#pragma unroll
            for (int off = 16; off > 0; off >>= 1) {
                float ov = __shfl_xor_sync(FULLMASK, bv, off);
                int oi = __shfl_xor_sync(FULLMASK, bi, off);
                if (ov > bv || (ov == bv && oi < bi)) { bv = ov; bi = oi; }
            }
            const int wl = bi >> 3, wj = bi & 7;
            if (lane == wl) takenmask |= 1 << wj;
            float selv = sig[0];
#pragma unroll
            for (int j = 1; j < 8; j++)
                if (j == wj) selv = sig[j];
            float wv = __shfl_sync(FULLMASK, selv, wl);
            wsel[rr] = wv; isel[rr] = bi; wsum += wv;
        }

        if (lane == 0) {
            const int token = bm + tl;
            float inv = 1.0f / wsum;
#pragma unroll
            for (int rr = 0; rr < 8; rr++) {
                outW[(size_t)token * 8 + rr] = wsel[rr] * inv * 2.5f;
                outI[(size_t)token * 8 + rr] = (float)isel[rr];
            }
        }
    }
}

// ------------------------------ launch -------------------------------------

extern "C" void kernel_launch(void* const* d_in, const int* in_sizes, int n_in,
                              void* d_out, int out_size) {
    const float* x = (const float*)d_in[0];       // [T, D]
    const float* weight = (const float*)d_in[1];  // [E, D]
    const float* bias = (const float*)d_in[2];    // [E]

    int E = in_sizes[2];           // 256
    int D = in_sizes[1] / E;       // 7168
    int T = in_sizes[0] / D;       // 8192

    void *pB0, *pB1;
    cudaGetSymbolAddress(&pB0, g_B0);
    cudaGetSymbolAddress(&pB1, g_B1);

    int n4 = E * D / 4;
    presplit_kernel<<<(n4 + 255) / 256, 256>>>(weight, (__half*)pB0, (__half*)pB1, n4);

    float* outW = (float*)d_out;
    float* outI = (float*)d_out + (size_t)T * 8;

    cudaFuncSetAttribute(moe_gate_kernel, cudaFuncAttributeMaxDynamicSharedMemorySize,
                         SMEM_BYTES);
    moe_gate_kernel<<<T / 64, 256, SMEM_BYTES>>>(x, (const __half*)pB0, (const __half*)pB1,
                                                 bias, outW, outI, T, E, D);
}

// round 14
// speedup vs baseline: 1.1041x; 1.1041x over previous
#include <cuda_runtime.h>
#include <cuda_fp16.h>
#include <math.h>
#include <stdint.h>

// ---------------------------------------------------------------------------
// Gate_14293651161746 (round 14): R12 + MMA scheduling fixes.
//   - MMA asm no longer volatile (ptxas may reorder/pipeline around HMMA latency)
//   - same-accumulator MMA distance >= 4 via hand interleave
//   W pre-split ONCE into two fp16 planes (64x main, 2048x residual scale).
//     a = a0 + a1s/2048 ; 64*b = b0 + b1s/2048
//     accA = sum a0*b0 ; accB = sum (a0*b1s + a1s*b0)
//     logit = (accA + accB/2048)/64, drained to fp32 SMEM every k=256
// Output: [weights (T*8) fp32][indices (T*8) as fp32]
// ---------------------------------------------------------------------------

#define FULLMASK 0xFFFFFFFFu
#define RSCALE 2048.0f
#define RSCALE_INV (1.0f / 2048.0f)
#define BSCALE 64.0f
#define BSCALE_INV (1.0f / 64.0f)

#define DD 7168
#define EE 256

static __device__ __half g_B0[(size_t)EE * DD];   // RN16(64*w)
static __device__ __half g_B1[(size_t)EE * DD];   // RN16((64w - b0)*2048)

// ---- SMEM layout ----------------------------------------------------------
// Stage buffer (fp16 tiles, rows padded to 40 halves = 80 B):
//   A0: 64 x 40 = 5120 B (off 0) | A1s: 5120 B (off 5120)
//   B0: 256 x 40 = 20480 B (off 10240) | B1s: 20480 B (off 30720)
// Two stages, then fp32 logits accumulator [64][264].
#define STAGE_BYTES 51200
#define LOGITS_OFF  102400
#define SMEM_BYTES  (102400 + 64 * 264 * 4)   // 169984

__device__ __forceinline__ uint32_t smem_to_u32(const void* p) {
    uint32_t a;
    asm("{ .reg .u64 t; cvta.to.shared.u64 t, %1; cvt.u32.u64 %0, t; }" : "=r"(a) : "l"(p));
    return a;
}

#define LDM4(r, addr) \
    asm volatile("ldmatrix.sync.aligned.m8n8.x4.shared.b16 {%0,%1,%2,%3}, [%4];" \
                 : "=r"((r)[0]), "=r"((r)[1]), "=r"((r)[2]), "=r"((r)[3]) \
                 : "r"(addr))

// NOT volatile: register-only in/out, lets ptxas schedule around HMMA latency
#define MMA16816(c, a, b0, b1) \
    asm("mma.sync.aligned.m16n8k16.row.col.f32.f16.f16.f32 " \
        "{%0,%1,%2,%3}, {%4,%5,%6,%7}, {%8,%9}, {%0,%1,%2,%3};" \
        : "+f"((c)[0]), "+f"((c)[1]), "+f"((c)[2]), "+f"((c)[3]) \
        : "r"((a)[0]), "r"((a)[1]), "r"((a)[2]), "r"((a)[3]), \
          "r"(b0), "r"(b1))

// split one float4 into main fp16 quad + scaled-residual fp16 quad
__device__ __forceinline__ void split4s(float4 v, uint2& lo, uint2& hi) {
    __half a0 = __float2half_rn(v.x), b0 = __float2half_rn(v.y);
    __half c0 = __float2half_rn(v.z), d0 = __float2half_rn(v.w);
    __half a1 = __float2half_rn((v.x - __half2float(a0)) * RSCALE);
    __half b1 = __float2half_rn((v.y - __half2float(b0)) * RSCALE);
    __half c1 = __float2half_rn((v.z - __half2float(c0)) * RSCALE);
    __half d1 = __float2half_rn((v.w - __half2float(d0)) * RSCALE);
    lo.x = (uint32_t)__half_as_ushort(a0) | ((uint32_t)__half_as_ushort(b0) << 16);
    lo.y = (uint32_t)__half_as_ushort(c0) | ((uint32_t)__half_as_ushort(d0) << 16);
    hi.x = (uint32_t)__half_as_ushort(a1) | ((uint32_t)__half_as_ushort(b1) << 16);
    hi.y = (uint32_t)__half_as_ushort(c1) | ((uint32_t)__half_as_ushort(d1) << 16);
}

// ---- presplit W -> two fp16 planes ----------------------------------------
__global__ void __launch_bounds__(256)
presplit_kernel(const float* __restrict__ W, __half* __restrict__ B0,
                __half* __restrict__ B1, int n4) {
    int i = blockIdx.x * blockDim.x + threadIdx.x;
    if (i >= n4) return;
    float4 v = ((const float4*)W)[i];
    v.x *= BSCALE; v.y *= BSCALE; v.z *= BSCALE; v.w *= BSCALE;
    uint2 lo, hi;
    split4s(v, lo, hi);
    ((uint2*)B0)[i] = lo;
    ((uint2*)B1)[i] = hi;
}

__global__ void __launch_bounds__(256, 1)
moe_gate_kernel(const float* __restrict__ X, const __half* __restrict__ B0g,
                const __half* __restrict__ B1g, const float* __restrict__ bias,
                float* __restrict__ outW, float* __restrict__ outI,
                int T, int E, int D) {
    extern __shared__ char smem[];
    const uint32_t sb = smem_to_u32(smem);
    const int tid = threadIdx.x;
    const int lane = tid & 31;
    const int wid = tid >> 5;
    const int wm = wid >> 2;   // 0..1  -> 32-row slice
    const int wn = wid & 3;    // 0..3  -> 64-col slice
    const int bm = blockIdx.x * 64;

    float* ls = (float*)(smem + LOGITS_OFF);   // [64][264] fp32 logits accumulator
#pragma unroll
    for (int i = 0; i < 66; i++) ls[tid + i * 256] = 0.0f;

    float accA[2][8][4];
    float accB[2][8][4];
#pragma unroll
    for (int i = 0; i < 2; i++)
#pragma unroll
        for (int j = 0; j < 8; j++)
#pragma unroll
            for (int k = 0; k < 4; k++) { accA[i][j][k] = 0.0f; accB[i][j][k] = 0.0f; }

    // A staging: element i = tid + j*256; row = i>>3, chunk col = (i&7)*4
    const int grow = tid >> 3;
    const int gcol = (tid & 7) * 4;
    const float* Ag = X + (size_t)(bm + grow) * D + gcol;
    const size_t jstride = (size_t)32 * D;
    const uint32_t sts_off = (uint32_t)(grow * 80 + (tid & 7) * 8);

    // B staging: per plane 256 rows x 2x16B chunks; thread -> row tid>>2 (+64/j)
    const int brow = tid >> 2;
    const int bchunk = (tid & 3) * 8;
    const __half* B0p = B0g + (size_t)brow * D + bchunk;
    const __half* B1p = B1g + (size_t)brow * D + bchunk;
    const uint32_t bdst = (uint32_t)(brow * 80 + bchunk * 2);
    const size_t bjstride = (size_t)64 * D;

    const int NS = D / 32;
    float4 ra[2];
    uint4 rb0[4], rb1[4];

    // ldmatrix per-thread base offsets (bytes within a stage buffer)
    const int q = lane >> 3;
    const uint32_t pa = (uint32_t)((wm * 32 + (q & 1) * 8 + (lane & 7)) * 80 + (q >> 1) * 16);
    const uint32_t pb = (uint32_t)((wn * 64 + ((q >> 1) & 1) * 8 + (lane & 7)) * 80 + (q & 1) * 16);

    // fragment element -> logits row/col (for chunk drains)
    const int drow = wm * 32 + (lane >> 2);
    const int dcol = wn * 64 + (lane & 3) * 2;

    // prologue LDG (stage 0)
#pragma unroll
    for (int j = 0; j < 2; j++) ra[j] = *(const float4*)(Ag + j * jstride);
#pragma unroll
    for (int j = 0; j < 4; j++) {
        rb0[j] = *(const uint4*)(B0p + j * bjstride);
        rb1[j] = *(const uint4*)(B1p + j * bjstride);
    }

    for (int s = 0; s < NS; s++) {
        const uint32_t boff = (uint32_t)((s & 1) * STAGE_BYTES);
        // ---- STS: A split fp32->fp16 pair; B raw 16B ---------------------
        {
            char* bufc = smem + boff;
#pragma unroll
            for (int j = 0; j < 2; j++) {
                uint2 lo, hi;
                split4s(ra[j], lo, hi);
                uint32_t o = sts_off + (uint32_t)j * (32 * 80);
                *(uint2*)(bufc + o) = lo;           // A0
                *(uint2*)(bufc + 5120 + o) = hi;    // A1s
            }
#pragma unroll
            for (int j = 0; j < 4; j++) {
                uint32_t o = bdst + (uint32_t)j * (64 * 80);
                *(uint4*)(bufc + 10240 + o) = rb0[j];   // B0
                *(uint4*)(bufc + 30720 + o) = rb1[j];   // B1s
            }
        }
        __syncthreads();

        // ---- LDG next stage (in flight during MMA) -----------------------
        if (s + 1 < NS) {
            const int k0 = (s + 1) * 32;
#pragma unroll
            for (int j = 0; j < 2; j++) ra[j] = *(const float4*)(Ag + k0 + j * jstride);
#pragma unroll
            for (int j = 0; j < 4; j++) {
                rb0[j] = *(const uint4*)(B0p + k0 + j * bjstride);
                rb1[j] = *(const uint4*)(B1p + k0 + j * bjstride);
            }
        }

        // ---- MMA over this stage: 2 k16-steps ----------------------------
        // per np group: accA x4 (both mt), cross1 x4, cross2 x4
        // -> same-accumulator distance >= 4 instructions
        const uint32_t abase = sb + boff + pa;
        const uint32_t bbase = sb + boff + 10240 + pb;
#pragma unroll
        for (int ks = 0; ks < 2; ks++) {
            uint32_t a0f[2][4], a1f[2][4];
#pragma unroll
            for (int mt = 0; mt < 2; mt++) {
                uint32_t aaddr = abase + (uint32_t)(mt * 1280 + ks * 32);
                LDM4(a0f[mt], aaddr);
                LDM4(a1f[mt], aaddr + 5120);
            }
#pragma unroll
            for (int np = 0; np < 4; np++) {
                uint32_t b0f[4], b1f[4];
                uint32_t baddr = bbase + (uint32_t)(np * 1280 + ks * 32);
                LDM4(b0f, baddr);
                LDM4(b1f, baddr + 20480);
                // main terms -> accA (4 independent accumulators)
#pragma unroll
                for (int mt = 0; mt < 2; mt++) {
                    MMA16816(accA[mt][2 * np],     a0f[mt], b0f[0], b0f[1]);
                    MMA16816(accA[mt][2 * np + 1], a0f[mt], b0f[2], b0f[3]);
                }
                // cross term 1 -> accB
#pragma unroll
                for (int mt = 0; mt < 2; mt++) {
                    MMA16816(accB[mt][2 * np],     a1f[mt], b0f[0], b0f[1]);
                    MMA16816(accB[mt][2 * np + 1], a1f[mt], b0f[2], b0f[3]);
                }
                // cross term 2 -> accB (distance 4 from cross term 1)
#pragma unroll
                for (int mt = 0; mt < 2; mt++) {
                    MMA16816(accB[mt][2 * np],     a0f[mt], b1f[0], b1f[1]);
                    MMA16816(accB[mt][2 * np + 1], a0f[mt], b1f[2], b1f[3]);
                }
            }
        }

        // ---- chunk drain every 8 stages (k=256): acc -> fp32 SMEM --------
        if ((s & 7) == 7) {
#pragma unroll
            for (int mt = 0; mt < 2; mt++) {
#pragma unroll
                for (int np = 0; np < 4; np++) {
#pragma unroll
                    for (int nt = 0; nt < 2; nt++) {
                        float* cA = accA[mt][2 * np + nt];
                        float* cB = accB[mt][2 * np + nt];
                        int row = drow + mt * 16;
                        int col = dcol + np * 16 + nt * 8;
                        ls[row * 264 + col]           += cA[0] + cB[0] * RSCALE_INV;
                        ls[row * 264 + col + 1]       += cA[1] + cB[1] * RSCALE_INV;
                        ls[(row + 8) * 264 + col]     += cA[2] + cB[2] * RSCALE_INV;
                        ls[(row + 8) * 264 + col + 1] += cA[3] + cB[3] * RSCALE_INV;
                        cA[0] = cA[1] = cA[2] = cA[3] = 0.0f;
                        cB[0] = cB[1] = cB[2] = cB[3] = 0.0f;
                    }
                }
            }
        }
        __syncthreads();
    }

    // ---- gate: one warp per token, 8 tokens per warp ----------------------
    float4 c0 = *(const float4*)(bias + lane * 8);
    float4 c1 = *(const float4*)(bias + lane * 8 + 4);
    const float bs[8] = {c0.x, c0.y, c0.z, c0.w, c1.x, c1.y, c1.z, c1.w};

    for (int r = 0; r < 8; r++) {
        const int tl = r * 8 + wid;
        const float* Lp = ls + tl * 264 + lane * 8;
        float4 v0 = *(const float4*)Lp;
        float4 v1 = *(const float4*)(Lp + 4);
        float lg[8] = {v0.x, v0.y, v0.z, v0.w, v1.x, v1.y, v1.z, v1.w};

        float sig[8], s[8];
#pragma unroll
        for (int j = 0; j < 8; j++) {
            float logit = lg[j] * BSCALE_INV;      // undo exact B pre-scale
            sig[j] = 1.0f / (1.0f + expf(-logit));
            s[j] = sig[j] + bs[j];
        }

        float t1 = -INFINITY, t2 = -INFINITY;
#pragma unroll
        for (int j = 0; j < 8; j++) {
            float v = s[j];
            if (v > t1) { t2 = t1; t1 = v; }
            else if (v > t2) { t2 = v; }
        }
#pragma unroll
        for (int off = 1; off < 4; off <<= 1) {
            float o1 = __shfl_xor_sync(FULLMASK, t1, off);
            float o2 = __shfl_xor_sync(FULLMASK, t2, off);
            float m1 = fmaxf(t1, o1);
            float m2 = fmaxf(fminf(t1, o1), (t1 > o1) ? t2 : o2);
            t1 = m1; t2 = m2;
        }
        float gsc = t1 + t2;

        float gs[8];
#pragma unroll
        for (int g = 0; g < 8; g++) gs[g] = __shfl_sync(FULLMASK, gsc, g * 4);

        int keepmask = 0;
#pragma unroll
        for (int rr = 0; rr < 4; rr++) {
            float best = -INFINITY; int bg = 0;
#pragma unroll
            for (int g = 0; g < 8; g++)
                if (!((keepmask >> g) & 1) && gs[g] > best) { best = gs[g]; bg = g; }
            keepmask |= 1 << bg;
        }
        const bool mk = (keepmask >> (lane >> 2)) & 1;
        float sm[8];
#pragma unroll
        for (int j = 0; j < 8; j++) sm[j] = mk ? s[j] : 0.0f;

        int takenmask = 0;
        float wsel[8]; int isel[8]; float wsum = 0.0f;
#pragma unroll
        for (int rr = 0; rr < 8; rr++) {
            float bv = -INFINITY; int bi = 0x7FFFFFFF;
#pragma unroll
            for (int j = 0; j < 8; j++)
                if (!((takenmask >> j) & 1) && sm[j] > bv) { bv = sm[j]; bi = lane * 8 + j; }
#pragma unroll
            for (int off = 16; off > 0; off >>= 1) {
                float ov = __shfl_xor_sync(FULLMASK, bv, off);
                int oi = __shfl_xor_sync(FULLMASK, bi, off);
                if (ov > bv || (ov == bv && oi < bi)) { bv = ov; bi = oi; }
            }
            const int wl = bi >> 3, wj = bi & 7;
            if (lane == wl) takenmask |= 1 << wj;
            float selv = sig[0];
#pragma unroll
            for (int j = 1; j < 8; j++)
                if (j == wj) selv = sig[j];
            float wv = __shfl_sync(FULLMASK, selv, wl);
            wsel[rr] = wv; isel[rr] = bi; wsum += wv;
        }

        if (lane == 0) {
            const int token = bm + tl;
            float inv = 1.0f / wsum;
#pragma unroll
            for (int rr = 0; rr < 8; rr++) {
                outW[(size_t)token * 8 + rr] = wsel[rr] * inv * 2.5f;
                outI[(size_t)token * 8 + rr] = (float)isel[rr];
            }
        }
    }
}

// ------------------------------ launch -------------------------------------

extern "C" void kernel_launch(void* const* d_in, const int* in_sizes, int n_in,
                              void* d_out, int out_size) {
    const float* x = (const float*)d_in[0];       // [T, D]
    const float* weight = (const float*)d_in[1];  // [E, D]
    const float* bias = (const float*)d_in[2];    // [E]

    int E = in_sizes[2];           // 256
    int D = in_sizes[1] / E;       // 7168
    int T = in_sizes[0] / D;       // 8192

    void *pB0, *pB1;
    cudaGetSymbolAddress(&pB0, g_B0);
    cudaGetSymbolAddress(&pB1, g_B1);

    int n4 = E * D / 4;
    presplit_kernel<<<(n4 + 255) / 256, 256>>>(weight, (__half*)pB0, (__half*)pB1, n4);

    float* outW = (float*)d_out;
    float* outI = (float*)d_out + (size_t)T * 8;

    cudaFuncSetAttribute(moe_gate_kernel, cudaFuncAttributeMaxDynamicSharedMemorySize,
                         SMEM_BYTES);
    moe_gate_kernel<<<T / 64, 256, SMEM_BYTES>>>(x, (const __half*)pB0, (const __half*)pB1,
                                                 bias, outW, outI, T, E, D);
}